// round 13
// baseline (speedup 1.0000x reference)
#include <cuda_runtime.h>
#include <cuda_fp16.h>
#include <cfloat>
#include <cstdint>

#define DIM      768
#define QN       64
#define TILE_M   128
#define CHUNK_K  64
#define NCHUNK   (DIM / CHUNK_K)     // 12
#define KSTEPS   (CHUNK_K / 16)      // 4
#define NTHREADS 384                 // 8 consumer warps + 4 producer warps
#define NCONS    256
#define NPROD    128
#define NBLOCKS  304                 // 2 per SM x 152 SMs
#define TOPK     5

// ---- smem: two 48KB pipeline buffers ----
// buffer: [A-hi 16KB][A-mid 16KB][B-hi 8KB][B-mid 8KB]
#define A_TILE    16384
#define B_TILE    8192
#define OFF_BB    (2 * A_TILE)
#define BUF_BYTES 49152
#define SMEM_DYN  (2 * BUF_BYTES + 1024)   // 99328; 2 CTAs = 198.6KB < 228KB
#define STAGE_STRIDE 68                    // floats; stage aliases consumed buffer

// ---------------- device scratch (no allocations allowed) ----------------
// q-splits pre-swizzled per-chunk SW128 tile images: [chunk][split][8KB]
__device__ uint4 g_qsw4[NCHUNK * 2 * B_TILE / 16];
__device__ float g_cand_val[NBLOCKS * QN * TOPK];
__device__ int   g_cand_idx[NBLOCKS * QN * TOPK];

// ---------------- helpers ----------------
__device__ __forceinline__ uint32_t smem_u32(const void* p) {
    uint32_t a;
    asm("{ .reg .u64 t; cvta.to.shared.u64 t, %1; cvt.u32.u64 %0, t; }" : "=r"(a) : "l"(p));
    return a;
}
#define SW128(off) ((off) ^ (((off) >> 3) & 0x70))

__device__ __forceinline__ void ldsm_x4(uint32_t* r, uint32_t addr) {
    asm volatile("ldmatrix.sync.aligned.m8n8.x4.shared.b16 {%0,%1,%2,%3}, [%4];"
        : "=r"(r[0]), "=r"(r[1]), "=r"(r[2]), "=r"(r[3]) : "r"(addr));
}
__device__ __forceinline__ void ldsm_x4_t(uint32_t* r, uint32_t addr) {
    asm volatile("ldmatrix.sync.aligned.m8n8.x4.trans.shared.b16 {%0,%1,%2,%3}, [%4];"
        : "=r"(r[0]), "=r"(r[1]), "=r"(r[2]), "=r"(r[3]) : "r"(addr));
}
__device__ __forceinline__ void mma_fp16(float* d, const uint32_t* a, const uint32_t* b) {
    asm volatile("mma.sync.aligned.m16n8k16.row.col.f32.f16.f16.f32 "
        "{%0,%1,%2,%3}, {%4,%5,%6,%7}, {%8,%9}, {%0,%1,%2,%3};"
        : "+f"(d[0]), "+f"(d[1]), "+f"(d[2]), "+f"(d[3])
        : "r"(a[0]), "r"(a[1]), "r"(a[2]), "r"(a[3]), "r"(b[0]), "r"(b[1]));
}

// strict ordering: higher value wins; ties -> lower index (matches lax.top_k)
__device__ __forceinline__ bool better(float av, int ai, float bv, int bi) {
    return (av > bv) || (av == bv && ai < bi);
}
__device__ __forceinline__ void topk_insert(float* tv, int* ti, float s, int idx) {
    if (!better(s, idx, tv[TOPK - 1], ti[TOPK - 1])) return;
    int pos = TOPK - 1;
    #pragma unroll
    for (int it = 0; it < TOPK - 1; it++) {
        if (pos > 0 && better(s, idx, tv[pos - 1], ti[pos - 1])) {
            tv[pos] = tv[pos - 1]; ti[pos] = ti[pos - 1]; pos--;
        }
    }
    tv[pos] = s; ti[pos] = idx;
}

// producer: fill one buffer with chunk (docbase, kb): A split tiles + B via cp.async
__device__ __forceinline__ void prod_fill(char* buf, uint32_t bufS,
                                          const float* __restrict__ emb,
                                          int chunk, int docbase, int kb,
                                          int ndocs, int ptid)
{
    // B tiles: 16KB identity copy of pre-swizzled chunk image (zero registers)
    const char* qsrc = (const char*)g_qsw4 + chunk * (2 * B_TILE);
    #pragma unroll
    for (int j = 0; j < 8; j++) {
        uint32_t dst = bufS + OFF_BB + (uint32_t)((ptid + j * NPROD) * 16);
        asm volatile("cp.async.ca.shared.global [%0], [%1], 16;"
                     :: "r"(dst), "l"(qsrc + (ptid + j * NPROD) * 16));
    }
    asm volatile("cp.async.commit_group;" ::: "memory");

    // A tiles: 2048 float4 / 128 threads = 16 each, in two batches of 8
    #pragma unroll
    for (int b = 0; b < 2; b++) {
        float4 v[8];
        #pragma unroll
        for (int j = 0; j < 8; j++) {
            int idx = ptid + (b * 8 + j) * NPROD;
            int row = idx >> 4, c4 = idx & 15;
            int gdoc = docbase + row;
            float4 x = make_float4(0.f, 0.f, 0.f, 0.f);
            if (gdoc < ndocs)
                x = *(const float4*)&emb[(size_t)gdoc * DIM + kb + c4 * 4];
            v[j] = x;
        }
        #pragma unroll
        for (int j = 0; j < 8; j++) {
            int idx = ptid + (b * 8 + j) * NPROD;
            uint32_t off = SW128((uint32_t)((idx >> 4) * 128 + (idx & 15) * 8));
            __half2 hA = __floats2half2_rn(v[j].x, v[j].y);
            __half2 hB = __floats2half2_rn(v[j].z, v[j].w);
            float r0 = v[j].x - __low2float(hA);
            float r1 = v[j].y - __high2float(hA);
            float r2 = v[j].z - __low2float(hB);
            float r3 = v[j].w - __high2float(hB);
            __half2 mA = __floats2half2_rn(r0, r1);
            __half2 mB = __floats2half2_rn(r2, r3);
            *(uint2*)(buf + off)          = make_uint2(*(uint32_t*)&hA, *(uint32_t*)&hB);
            *(uint2*)(buf + A_TILE + off) = make_uint2(*(uint32_t*)&mA, *(uint32_t*)&mB);
        }
    }
    asm volatile("cp.async.wait_group 0;" ::: "memory");
}

// ---------------- kernel 1: q = query @ W^T + b -> 2 fp16 splits, pre-swizzled tiles ----------------
#define QP_KC 64
#define QP_ROWS 8
__global__ __launch_bounds__(256) void qproj_kernel(
    const float* __restrict__ query, const float* __restrict__ W, const float* __restrict__ bias)
{
    __shared__ float sW[QP_ROWS][QP_KC];
    __shared__ float sQ[QN][QP_KC + 1];

    int tid = threadIdx.x;
    int dbase = blockIdx.x * QP_ROWS;
    int q  = tid & 63;
    int dg = tid >> 6;

    float acc[2] = {0.f, 0.f};

    for (int kb = 0; kb < DIM; kb += QP_KC) {
        __syncthreads();
        if (tid < QP_ROWS * 16) {
            int row = tid >> 4, c4 = tid & 15;
            float4 v = *(const float4*)&W[(size_t)(dbase + row) * DIM + kb + c4 * 4];
            sW[row][c4*4+0]=v.x; sW[row][c4*4+1]=v.y; sW[row][c4*4+2]=v.z; sW[row][c4*4+3]=v.w;
        }
        #pragma unroll
        for (int i = 0; i < 4; i++) {
            int idx = tid + i * 256;
            int row = idx >> 4, c4 = idx & 15;
            float4 v = *(const float4*)&query[(size_t)row * DIM + kb + c4 * 4];
            sQ[row][c4*4+0]=v.x; sQ[row][c4*4+1]=v.y; sQ[row][c4*4+2]=v.z; sQ[row][c4*4+3]=v.w;
        }
        __syncthreads();
        #pragma unroll 8
        for (int k = 0; k < QP_KC; k++) {
            float qv = sQ[q][k];
            #pragma unroll
            for (int i = 0; i < 2; i++) acc[i] += sW[dg * 2 + i][k] * qv;
        }
    }

    unsigned char* qsw = (unsigned char*)g_qsw4;
    #pragma unroll
    for (int i = 0; i < 2; i++) {
        int d = dbase + dg * 2 + i;
        float val = acc[i] + bias[d];
        __half h = __float2half_rn(val);
        float r  = val - __half2float(h);            // exact residual
        __half m = __float2half_rn(r);
        int cch = d >> 6;
        int rr  = d & 63;
        uint32_t off = SW128((uint32_t)(rr * 128 + q * 2));
        *(unsigned short*)(qsw + cch * (2 * B_TILE) + off)          = __half_as_ushort(h);
        *(unsigned short*)(qsw + cch * (2 * B_TILE) + B_TILE + off) = __half_as_ushort(m);
    }
}

// ---------------- kernel 2: warp-specialized fp16 2-split scores + fused top-5 ----------------
__global__ __launch_bounds__(NTHREADS, 2) void score_topk_kernel(
    const float* __restrict__ emb, int ndocs, int ntiles)
{
    extern __shared__ char dynsmem[];
    __shared__ float topv[QN][TOPK];
    __shared__ int   topi[QN][TOPK];

    int tid  = threadIdx.x;
    int lane = tid & 31;
    bool isProd = (tid >= NCONS);
    int ptid = tid - NCONS;

    uint32_t raw  = smem_u32(dynsmem);
    uint32_t base = (raw + 1023) & ~1023u;
    char*    pool = dynsmem + (base - raw);

    if (tid < QN) {
        #pragma unroll
        for (int j = 0; j < TOPK; j++) { topv[tid][j] = -FLT_MAX; topi[tid][j] = 0x7fffffff; }
    }

    // consumer geometry
    int w = tid >> 5;
    int m_base = (w >> 1) * 32;
    int n_base = (w & 1) * 32;
    int l15 = lane & 15;
    int lh8 = (lane >> 4) * 8;

    float acc[2][4][4];
    #pragma unroll
    for (int mi = 0; mi < 2; mi++)
        #pragma unroll
        for (int ni = 0; ni < 4; ni++)
            #pragma unroll
            for (int r = 0; r < 4; r++) acc[mi][ni][r] = 0.f;

    int t = blockIdx.x;
    int c = 0, p = 0;

    if (t < ntiles) {
        // prologue: producers fill buf 0 with (t, 0)
        if (isProd)
            prod_fill(pool, base, emb, 0, t * TILE_M, 0, ndocs, ptid);
        __syncthreads();

        while (true) {
            int cn = c + 1, tn = t;
            bool more = true;
            if (cn == NCHUNK) { cn = 0; tn = t + gridDim.x; more = (tn < ntiles); }

            char*    bufc  = pool + p * BUF_BYTES;
            uint32_t bufcS = base + (uint32_t)(p * BUF_BYTES);

            if (isProd) {
                if (more)
                    prod_fill(pool + (p ^ 1) * BUF_BYTES, base + (uint32_t)((p ^ 1) * BUF_BYTES),
                              emb, cn, tn * TILE_M, cn * CHUNK_K, ndocs, ptid);
            } else {
                // MMA phase on bufc
                for (int ks = 0; ks < KSTEPS; ks++) {
                    uint32_t Af[2][2][4];
                    uint32_t Bf[2][8];
                    uint32_t aoff0 = SW128((uint32_t)((m_base + l15) * 128 + (ks * 16 + lh8) * 2));
                    uint32_t aoff1 = SW128((uint32_t)((m_base + 16 + l15) * 128 + (ks * 16 + lh8) * 2));
                    uint32_t boff0 = SW128((uint32_t)((ks * 16 + l15) * 128 + (n_base + lh8) * 2));
                    uint32_t boff1 = SW128((uint32_t)((ks * 16 + l15) * 128 + (n_base + 16 + lh8) * 2));
                    #pragma unroll
                    for (int s = 0; s < 2; s++) {
                        ldsm_x4  (Af[s][0],  bufcS + s * A_TILE + aoff0);
                        ldsm_x4  (Af[s][1],  bufcS + s * A_TILE + aoff1);
                        ldsm_x4_t(&Bf[s][0], bufcS + OFF_BB + s * B_TILE + boff0);
                        ldsm_x4_t(&Bf[s][4], bufcS + OFF_BB + s * B_TILE + boff1);
                    }
                    const int sa[3] = {0, 0, 1};   // hh, hm, mh
                    const int sb[3] = {0, 1, 0};
                    #pragma unroll
                    for (int pp = 0; pp < 3; pp++)
                        #pragma unroll
                        for (int mi = 0; mi < 2; mi++)
                            #pragma unroll
                            for (int ni = 0; ni < 4; ni++)
                                mma_fp16(acc[mi][ni], Af[sa[pp]][mi], &Bf[sb[pp]][ni * 2]);
                }

                if (c == NCHUNK - 1) {
                    // tile epilogue: stage aliases bufc (consumed); producers are in buf p^1
                    float* stage = (float*)bufc;
                    asm volatile("bar.sync 1, %0;" :: "n"(NCONS) : "memory");  // all consumer reads done
                    #pragma unroll
                    for (int mi = 0; mi < 2; mi++)
                        #pragma unroll
                        for (int ni = 0; ni < 4; ni++) {
                            int row = m_base + mi * 16 + (lane >> 2);
                            int col = n_base + ni * 8 + (lane & 3) * 2;
                            *(float2*)&stage[row * STAGE_STRIDE + col] =
                                make_float2(acc[mi][ni][0], acc[mi][ni][1]);
                            *(float2*)&stage[(row + 8) * STAGE_STRIDE + col] =
                                make_float2(acc[mi][ni][2], acc[mi][ni][3]);
                        }
                    asm volatile("bar.sync 1, %0;" :: "n"(NCONS) : "memory");  // stage visible
                    if (tid < QN) {
                        float* tv = topv[tid];
                        int*   ti = topi[tid];
                        int docbase = t * TILE_M;
                        int dmax = ndocs - docbase;
                        if (dmax > TILE_M) dmax = TILE_M;
                        for (int dl = 0; dl < dmax; dl++) {
                            float s = stage[dl * STAGE_STRIDE + tid];
                            if (s > tv[TOPK - 1]) topk_insert(tv, ti, s, docbase + dl);
                        }
                    }
                    #pragma unroll
                    for (int mi = 0; mi < 2; mi++)
                        #pragma unroll
                        for (int ni = 0; ni < 4; ni++)
                            #pragma unroll
                            for (int r = 0; r < 4; r++) acc[mi][ni][r] = 0.f;
                }
            }

            __syncthreads();   // buf p^1 ready for consumers; buf p free for producers
            if (!more) break;
            t = tn; c = cn; p ^= 1;
        }
    }

    __syncthreads();
    if (tid < QN) {
        #pragma unroll
        for (int j = 0; j < TOPK; j++) {
            size_t o = ((size_t)blockIdx.x * QN + tid) * TOPK + j;
            g_cand_val[o] = topv[tid][j];
            g_cand_idx[o] = topi[tid][j];
        }
    }
}

// ---------------- kernel 3: global candidate merge -> output (float indices) ----------------
__global__ __launch_bounds__(128) void final_topk_kernel(float* __restrict__ out, int nblocks)
{
    __shared__ float sval[128 * TOPK];
    __shared__ int   sidx[128 * TOPK];
    int q   = blockIdx.x;
    int tid = threadIdx.x;

    float lv[TOPK]; int li[TOPK];
    #pragma unroll
    for (int j = 0; j < TOPK; j++) { lv[j] = -FLT_MAX; li[j] = 0x7fffffff; }

    for (int b = tid; b < nblocks; b += 128) {
        size_t o = ((size_t)b * QN + q) * TOPK;
        #pragma unroll
        for (int j = 0; j < TOPK; j++)
            topk_insert(lv, li, g_cand_val[o + j], g_cand_idx[o + j]);
    }
    #pragma unroll
    for (int j = 0; j < TOPK; j++) { sval[tid * TOPK + j] = lv[j]; sidx[tid * TOPK + j] = li[j]; }
    __syncthreads();

    if (tid == 0) {
        float fv[TOPK]; int fi[TOPK];
        #pragma unroll
        for (int j = 0; j < TOPK; j++) { fv[j] = -FLT_MAX; fi[j] = 0x7fffffff; }
        for (int e = 0; e < 128 * TOPK; e++)
            topk_insert(fv, fi, sval[e], sidx[e]);
        #pragma unroll
        for (int j = 0; j < TOPK; j++) out[q * TOPK + j] = (float)fi[j];
    }
}

// ---------------- launch ----------------
// Inputs identified BY ELEMENT COUNT:
//   b = 768, query = 49152, W = 589824, block_emb = largest, top_k scalar ignored (TOPK=5 per out_size).
extern "C" void kernel_launch(void* const* d_in, const int* in_sizes, int n_in,
                              void* d_out, int out_size)
{
    const float *query = nullptr, *W = nullptr, *bias = nullptr, *emb = nullptr;
    int ndocs = 0;
    for (int i = 0; i < n_in; i++) {
        int sz = in_sizes[i];
        if      (sz == DIM)        bias  = (const float*)d_in[i];
        else if (sz == QN * DIM)   query = (const float*)d_in[i];
        else if (sz == DIM * DIM)  W     = (const float*)d_in[i];
        else if (sz >  DIM * DIM) { emb  = (const float*)d_in[i]; ndocs = sz / DIM; }
    }
    if (!query || !W || !bias || !emb || ndocs <= 0) return;

    int ntiles = (ndocs + TILE_M - 1) / TILE_M;

    cudaFuncSetAttribute(score_topk_kernel, cudaFuncAttributeMaxDynamicSharedMemorySize, SMEM_DYN);

    qproj_kernel<<<DIM / QP_ROWS, 256>>>(query, W, bias);
    score_topk_kernel<<<NBLOCKS, NTHREADS, SMEM_DYN>>>(emb, ndocs, ntiles);
    final_topk_kernel<<<QN, 128>>>((float*)d_out, NBLOCKS);
}

// round 14
// speedup vs baseline: 1.1766x; 1.1766x over previous
#include <cuda_runtime.h>
#include <cuda_fp16.h>
#include <cfloat>
#include <cstdint>

#define DIM      768
#define QN       64
#define TILE_M   128
#define CHUNK_K  64
#define NCHUNK   (DIM / CHUNK_K)     // 12
#define KSTEPS   (CHUNK_K / 16)      // 4
#define NTHREADS 320                 // 8 consumer warps + 2 producer warps
#define NCONS    256
#define NPROD    64
#define NBLOCKS  304                 // 2 per SM x 152 SMs
#define TOPK     5

// ---- smem: two 48KB pipeline buffers ----
// buffer: [A-hi 16KB][A-mid 16KB][B-hi 8KB][B-mid 8KB]
#define A_TILE    16384
#define B_TILE    8192
#define OFF_BB    (2 * A_TILE)
#define BUF_BYTES 49152
#define SMEM_DYN  (2 * BUF_BYTES + 1024)   // 99328/CTA; 2 CTAs = 198.6KB < 228KB
#define STAGE_STRIDE 68                    // floats; stage aliases consumed buffer

// ---------------- device scratch (no allocations allowed) ----------------
// q-splits pre-swizzled per-chunk SW128 tile images: [chunk][split][8KB]
__device__ uint4 g_qsw4[NCHUNK * 2 * B_TILE / 16];
__device__ float g_cand_val[NBLOCKS * QN * TOPK];
__device__ int   g_cand_idx[NBLOCKS * QN * TOPK];

// ---------------- helpers ----------------
__device__ __forceinline__ uint32_t smem_u32(const void* p) {
    uint32_t a;
    asm("{ .reg .u64 t; cvta.to.shared.u64 t, %1; cvt.u32.u64 %0, t; }" : "=r"(a) : "l"(p));
    return a;
}
#define SW128(off) ((off) ^ (((off) >> 3) & 0x70))

__device__ __forceinline__ void ldsm_x4(uint32_t* r, uint32_t addr) {
    asm volatile("ldmatrix.sync.aligned.m8n8.x4.shared.b16 {%0,%1,%2,%3}, [%4];"
        : "=r"(r[0]), "=r"(r[1]), "=r"(r[2]), "=r"(r[3]) : "r"(addr));
}
__device__ __forceinline__ void ldsm_x4_t(uint32_t* r, uint32_t addr) {
    asm volatile("ldmatrix.sync.aligned.m8n8.x4.trans.shared.b16 {%0,%1,%2,%3}, [%4];"
        : "=r"(r[0]), "=r"(r[1]), "=r"(r[2]), "=r"(r[3]) : "r"(addr));
}
__device__ __forceinline__ void mma_fp16(float* d, const uint32_t* a, const uint32_t* b) {
    asm volatile("mma.sync.aligned.m16n8k16.row.col.f32.f16.f16.f32 "
        "{%0,%1,%2,%3}, {%4,%5,%6,%7}, {%8,%9}, {%0,%1,%2,%3};"
        : "+f"(d[0]), "+f"(d[1]), "+f"(d[2]), "+f"(d[3])
        : "r"(a[0]), "r"(a[1]), "r"(a[2]), "r"(a[3]), "r"(b[0]), "r"(b[1]));
}

// strict ordering: higher value wins; ties -> lower index (matches lax.top_k)
__device__ __forceinline__ bool better(float av, int ai, float bv, int bi) {
    return (av > bv) || (av == bv && ai < bi);
}
__device__ __forceinline__ void topk_insert(float* tv, int* ti, float s, int idx) {
    if (!better(s, idx, tv[TOPK - 1], ti[TOPK - 1])) return;
    int pos = TOPK - 1;
    #pragma unroll
    for (int it = 0; it < TOPK - 1; it++) {
        if (pos > 0 && better(s, idx, tv[pos - 1], ti[pos - 1])) {
            tv[pos] = tv[pos - 1]; ti[pos] = ti[pos - 1]; pos--;
        }
    }
    tv[pos] = s; ti[pos] = idx;
}

// producer batch load: 8 float4 for batch b
__device__ __forceinline__ void prod_ldg(float4* v, const float* __restrict__ emb,
                                         int docbase, int kb, int ndocs, int ptid, int b) {
    #pragma unroll
    for (int j = 0; j < 8; j++) {
        int idx = ptid + (b * 8 + j) * NPROD;
        int row = idx >> 4, c4 = idx & 15;
        int gdoc = docbase + row;
        float4 x = make_float4(0.f, 0.f, 0.f, 0.f);
        if (gdoc < ndocs)
            x = *(const float4*)&emb[(size_t)gdoc * DIM + kb + c4 * 4];
        v[j] = x;
    }
}
// producer batch convert + STS
__device__ __forceinline__ void prod_sts(const float4* v, char* buf, int ptid, int b) {
    #pragma unroll
    for (int j = 0; j < 8; j++) {
        int idx = ptid + (b * 8 + j) * NPROD;
        uint32_t off = SW128((uint32_t)((idx >> 4) * 128 + (idx & 15) * 8));
        __half2 hA = __floats2half2_rn(v[j].x, v[j].y);
        __half2 hB = __floats2half2_rn(v[j].z, v[j].w);
        float r0 = v[j].x - __low2float(hA);
        float r1 = v[j].y - __high2float(hA);
        float r2 = v[j].z - __low2float(hB);
        float r3 = v[j].w - __high2float(hB);
        __half2 mA = __floats2half2_rn(r0, r1);
        __half2 mB = __floats2half2_rn(r2, r3);
        *(uint2*)(buf + off)          = make_uint2(*(uint32_t*)&hA, *(uint32_t*)&hB);
        *(uint2*)(buf + A_TILE + off) = make_uint2(*(uint32_t*)&mA, *(uint32_t*)&mB);
    }
}

// producer: fill one buffer with chunk (docbase, kb); 2-deep batch pipeline
__device__ __forceinline__ void prod_fill(char* buf, uint32_t bufS,
                                          const float* __restrict__ emb,
                                          int chunk, int docbase, int kb,
                                          int ndocs, int ptid)
{
    // B tiles: 16KB identity copy of pre-swizzled chunk image (zero registers)
    const char* qsrc = (const char*)g_qsw4 + chunk * (2 * B_TILE);
    #pragma unroll
    for (int j = 0; j < 16; j++) {
        uint32_t dst = bufS + OFF_BB + (uint32_t)((ptid + j * NPROD) * 16);
        asm volatile("cp.async.ca.shared.global [%0], [%1], 16;"
                     :: "r"(dst), "l"(qsrc + (ptid + j * NPROD) * 16));
    }
    asm volatile("cp.async.commit_group;" ::: "memory");

    // A tiles: 2048 float4 / 64 threads = 32 each, 4 batches of 8, pipelined depth 2
    float4 cur[8], nxt[8];
    prod_ldg(cur, emb, docbase, kb, ndocs, ptid, 0);
    #pragma unroll
    for (int b = 0; b < 4; b++) {
        if (b < 3) prod_ldg(nxt, emb, docbase, kb, ndocs, ptid, b + 1);
        prod_sts(cur, buf, ptid, b);
        if (b < 3) {
            #pragma unroll
            for (int j = 0; j < 8; j++) cur[j] = nxt[j];
        }
    }
    asm volatile("cp.async.wait_group 0;" ::: "memory");
}

// ---------------- kernel 1: q = query @ W^T + b -> 2 fp16 splits, pre-swizzled tiles ----------------
#define QP_KC 64
#define QP_ROWS 8
__global__ __launch_bounds__(256) void qproj_kernel(
    const float* __restrict__ query, const float* __restrict__ W, const float* __restrict__ bias)
{
    __shared__ float sW[QP_ROWS][QP_KC];
    __shared__ float sQ[QN][QP_KC + 1];

    int tid = threadIdx.x;
    int dbase = blockIdx.x * QP_ROWS;
    int q  = tid & 63;
    int dg = tid >> 6;

    float acc[2] = {0.f, 0.f};

    for (int kb = 0; kb < DIM; kb += QP_KC) {
        __syncthreads();
        if (tid < QP_ROWS * 16) {
            int row = tid >> 4, c4 = tid & 15;
            float4 v = *(const float4*)&W[(size_t)(dbase + row) * DIM + kb + c4 * 4];
            sW[row][c4*4+0]=v.x; sW[row][c4*4+1]=v.y; sW[row][c4*4+2]=v.z; sW[row][c4*4+3]=v.w;
        }
        #pragma unroll
        for (int i = 0; i < 4; i++) {
            int idx = tid + i * 256;
            int row = idx >> 4, c4 = idx & 15;
            float4 v = *(const float4*)&query[(size_t)row * DIM + kb + c4 * 4];
            sQ[row][c4*4+0]=v.x; sQ[row][c4*4+1]=v.y; sQ[row][c4*4+2]=v.z; sQ[row][c4*4+3]=v.w;
        }
        __syncthreads();
        #pragma unroll 8
        for (int k = 0; k < QP_KC; k++) {
            float qv = sQ[q][k];
            #pragma unroll
            for (int i = 0; i < 2; i++) acc[i] += sW[dg * 2 + i][k] * qv;
        }
    }

    unsigned char* qsw = (unsigned char*)g_qsw4;
    #pragma unroll
    for (int i = 0; i < 2; i++) {
        int d = dbase + dg * 2 + i;
        float val = acc[i] + bias[d];
        __half h = __float2half_rn(val);
        float r  = val - __half2float(h);            // exact residual
        __half m = __float2half_rn(r);
        int cch = d >> 6;
        int rr  = d & 63;
        uint32_t off = SW128((uint32_t)(rr * 128 + q * 2));
        *(unsigned short*)(qsw + cch * (2 * B_TILE) + off)          = __half_as_ushort(h);
        *(unsigned short*)(qsw + cch * (2 * B_TILE) + B_TILE + off) = __half_as_ushort(m);
    }
}

// ---------------- kernel 2: warp-specialized fp16 2-split scores + fused top-5 ----------------
__global__ __launch_bounds__(NTHREADS, 2) void score_topk_kernel(
    const float* __restrict__ emb, int ndocs, int ntiles)
{
    extern __shared__ char dynsmem[];
    __shared__ float topv[QN][TOPK];
    __shared__ int   topi[QN][TOPK];

    int tid  = threadIdx.x;
    int lane = tid & 31;
    bool isProd = (tid >= NCONS);
    int ptid = tid - NCONS;

    uint32_t raw  = smem_u32(dynsmem);
    uint32_t base = (raw + 1023) & ~1023u;
    char*    pool = dynsmem + (base - raw);

    if (tid < QN) {
        #pragma unroll
        for (int j = 0; j < TOPK; j++) { topv[tid][j] = -FLT_MAX; topi[tid][j] = 0x7fffffff; }
    }

    // consumer geometry
    int w = tid >> 5;
    int m_base = (w >> 1) * 32;
    int n_base = (w & 1) * 32;
    int l15 = lane & 15;
    int lh8 = (lane >> 4) * 8;

    float acc[2][4][4];
    #pragma unroll
    for (int mi = 0; mi < 2; mi++)
        #pragma unroll
        for (int ni = 0; ni < 4; ni++)
            #pragma unroll
            for (int r = 0; r < 4; r++) acc[mi][ni][r] = 0.f;

    int t = blockIdx.x;
    int c = 0, p = 0;

    if (t < ntiles) {
        // prologue: producers fill buf 0 with (t, 0)
        if (isProd)
            prod_fill(pool, base, emb, 0, t * TILE_M, 0, ndocs, ptid);
        __syncthreads();

        while (true) {
            int cn = c + 1, tn = t;
            bool more = true;
            if (cn == NCHUNK) { cn = 0; tn = t + gridDim.x; more = (tn < ntiles); }

            char*    bufc  = pool + p * BUF_BYTES;
            uint32_t bufcS = base + (uint32_t)(p * BUF_BYTES);

            if (isProd) {
                if (more)
                    prod_fill(pool + (p ^ 1) * BUF_BYTES, base + (uint32_t)((p ^ 1) * BUF_BYTES),
                              emb, cn, tn * TILE_M, cn * CHUNK_K, ndocs, ptid);
            } else {
                // MMA phase on bufc
                for (int ks = 0; ks < KSTEPS; ks++) {
                    uint32_t Af[2][2][4];
                    uint32_t Bf[2][8];
                    uint32_t aoff0 = SW128((uint32_t)((m_base + l15) * 128 + (ks * 16 + lh8) * 2));
                    uint32_t aoff1 = SW128((uint32_t)((m_base + 16 + l15) * 128 + (ks * 16 + lh8) * 2));
                    uint32_t boff0 = SW128((uint32_t)((ks * 16 + l15) * 128 + (n_base + lh8) * 2));
                    uint32_t boff1 = SW128((uint32_t)((ks * 16 + l15) * 128 + (n_base + 16 + lh8) * 2));
                    #pragma unroll
                    for (int s = 0; s < 2; s++) {
                        ldsm_x4  (Af[s][0],  bufcS + s * A_TILE + aoff0);
                        ldsm_x4  (Af[s][1],  bufcS + s * A_TILE + aoff1);
                        ldsm_x4_t(&Bf[s][0], bufcS + OFF_BB + s * B_TILE + boff0);
                        ldsm_x4_t(&Bf[s][4], bufcS + OFF_BB + s * B_TILE + boff1);
                    }
                    const int sa[3] = {0, 0, 1};   // hh, hm, mh
                    const int sb[3] = {0, 1, 0};
                    #pragma unroll
                    for (int pp = 0; pp < 3; pp++)
                        #pragma unroll
                        for (int mi = 0; mi < 2; mi++)
                            #pragma unroll
                            for (int ni = 0; ni < 4; ni++)
                                mma_fp16(acc[mi][ni], Af[sa[pp]][mi], &Bf[sb[pp]][ni * 2]);
                }

                if (c == NCHUNK - 1) {
                    // tile epilogue: stage aliases bufc (consumed); producers are in buf p^1
                    float* stage = (float*)bufc;
                    asm volatile("bar.sync 1, %0;" :: "n"(NCONS) : "memory");  // consumer reads done
                    #pragma unroll
                    for (int mi = 0; mi < 2; mi++)
                        #pragma unroll
                        for (int ni = 0; ni < 4; ni++) {
                            int row = m_base + mi * 16 + (lane >> 2);
                            int col = n_base + ni * 8 + (lane & 3) * 2;
                            *(float2*)&stage[row * STAGE_STRIDE + col] =
                                make_float2(acc[mi][ni][0], acc[mi][ni][1]);
                            *(float2*)&stage[(row + 8) * STAGE_STRIDE + col] =
                                make_float2(acc[mi][ni][2], acc[mi][ni][3]);
                        }
                    asm volatile("bar.sync 1, %0;" :: "n"(NCONS) : "memory");  // stage visible
                    if (tid < QN) {
                        float* tv = topv[tid];
                        int*   ti = topi[tid];
                        int docbase = t * TILE_M;
                        int dmax = ndocs - docbase;
                        if (dmax > TILE_M) dmax = TILE_M;
                        for (int dl = 0; dl < dmax; dl++) {
                            float s = stage[dl * STAGE_STRIDE + tid];
                            if (s > tv[TOPK - 1]) topk_insert(tv, ti, s, docbase + dl);
                        }
                    }
                    #pragma unroll
                    for (int mi = 0; mi < 2; mi++)
                        #pragma unroll
                        for (int ni = 0; ni < 4; ni++)
                            #pragma unroll
                            for (int r = 0; r < 4; r++) acc[mi][ni][r] = 0.f;
                }
            }

            __syncthreads();   // buf p^1 ready for consumers; buf p free for producers
            if (!more) break;
            t = tn; c = cn; p ^= 1;
        }
    }

    __syncthreads();
    if (tid < QN) {
        #pragma unroll
        for (int j = 0; j < TOPK; j++) {
            size_t o = ((size_t)blockIdx.x * QN + tid) * TOPK + j;
            g_cand_val[o] = topv[tid][j];
            g_cand_idx[o] = topi[tid][j];
        }
    }
}

// ---------------- kernel 3: global candidate merge -> output (float indices) ----------------
__global__ __launch_bounds__(128) void final_topk_kernel(float* __restrict__ out, int nblocks)
{
    __shared__ float sval[128 * TOPK];
    __shared__ int   sidx[128 * TOPK];
    int q   = blockIdx.x;
    int tid = threadIdx.x;

    float lv[TOPK]; int li[TOPK];
    #pragma unroll
    for (int j = 0; j < TOPK; j++) { lv[j] = -FLT_MAX; li[j] = 0x7fffffff; }

    for (int b = tid; b < nblocks; b += 128) {
        size_t o = ((size_t)b * QN + q) * TOPK;
        #pragma unroll
        for (int j = 0; j < TOPK; j++)
            topk_insert(lv, li, g_cand_val[o + j], g_cand_idx[o + j]);
    }
    #pragma unroll
    for (int j = 0; j < TOPK; j++) { sval[tid * TOPK + j] = lv[j]; sidx[tid * TOPK + j] = li[j]; }
    __syncthreads();

    if (tid == 0) {
        float fv[TOPK]; int fi[TOPK];
        #pragma unroll
        for (int j = 0; j < TOPK; j++) { fv[j] = -FLT_MAX; fi[j] = 0x7fffffff; }
        for (int e = 0; e < 128 * TOPK; e++)
            topk_insert(fv, fi, sval[e], sidx[e]);
        #pragma unroll
        for (int j = 0; j < TOPK; j++) out[q * TOPK + j] = (float)fi[j];
    }
}

// ---------------- launch ----------------
// Inputs identified BY ELEMENT COUNT:
//   b = 768, query = 49152, W = 589824, block_emb = largest, top_k scalar ignored (TOPK=5 per out_size).
extern "C" void kernel_launch(void* const* d_in, const int* in_sizes, int n_in,
                              void* d_out, int out_size)
{
    const float *query = nullptr, *W = nullptr, *bias = nullptr, *emb = nullptr;
    int ndocs = 0;
    for (int i = 0; i < n_in; i++) {
        int sz = in_sizes[i];
        if      (sz == DIM)        bias  = (const float*)d_in[i];
        else if (sz == QN * DIM)   query = (const float*)d_in[i];
        else if (sz == DIM * DIM)  W     = (const float*)d_in[i];
        else if (sz >  DIM * DIM) { emb  = (const float*)d_in[i]; ndocs = sz / DIM; }
    }
    if (!query || !W || !bias || !emb || ndocs <= 0) return;

    int ntiles = (ndocs + TILE_M - 1) / TILE_M;

    cudaFuncSetAttribute(score_topk_kernel, cudaFuncAttributeMaxDynamicSharedMemorySize, SMEM_DYN);

    qproj_kernel<<<DIM / QP_ROWS, 256>>>(query, W, bias);
    score_topk_kernel<<<NBLOCKS, NTHREADS, SMEM_DYN>>>(emb, ndocs, ntiles);
    final_topk_kernel<<<QN, 128>>>((float*)d_out, NBLOCKS);
}

// round 15
// speedup vs baseline: 1.4588x; 1.2399x over previous
#include <cuda_runtime.h>
#include <cuda_fp16.h>
#include <cfloat>
#include <cstdint>

#define DIM      768
#define QN       64
#define TILE_M   128
#define CHUNK_K  64
#define NCHUNK   (DIM / CHUNK_K)     // 12
#define KSTEPS   (CHUNK_K / 16)      // 4
#define NTHREADS 256
#define NBLOCKS  304                 // 2 per SM x 152 SMs
#define TOPK     5

// ---- smem layout: [B buf0 16KB][B buf1 16KB][stage 34.8KB] ----
#define B_SPLIT   8192                          // one split tile: 64 k-rows x 128B SW128
#define B_CHUNK   (2 * B_SPLIT)                 // 16KB per chunk (hi+mid)
#define OFF_STAGE (2 * B_CHUNK)                 // 32768
#define STAGE_STRIDE 68
#define STAGE_BYTES  (TILE_M * STAGE_STRIDE * 4)   // 34816
#define SMEM_DYN  (OFF_STAGE + STAGE_BYTES + 1024) // 68608/CTA; 2 CTAs = 137KB

// ---------------- device scratch (no allocations allowed) ----------------
// q-splits pre-swizzled per-chunk SW128 tile images: [chunk][split][8KB]
__device__ uint4 g_qsw4[NCHUNK * B_CHUNK / 16];
__device__ float g_cand_val[NBLOCKS * QN * TOPK];
__device__ int   g_cand_idx[NBLOCKS * QN * TOPK];

// ---------------- helpers ----------------
__device__ __forceinline__ uint32_t smem_u32(const void* p) {
    uint32_t a;
    asm("{ .reg .u64 t; cvta.to.shared.u64 t, %1; cvt.u32.u64 %0, t; }" : "=r"(a) : "l"(p));
    return a;
}
#define SW128(off) ((off) ^ (((off) >> 3) & 0x70))

__device__ __forceinline__ void ldsm_x4_t(uint32_t* r, uint32_t addr) {
    asm volatile("ldmatrix.sync.aligned.m8n8.x4.trans.shared.b16 {%0,%1,%2,%3}, [%4];"
        : "=r"(r[0]), "=r"(r[1]), "=r"(r[2]), "=r"(r[3]) : "r"(addr));
}
__device__ __forceinline__ void mma_fp16(float* d, const uint32_t* a, const uint32_t* b) {
    asm volatile("mma.sync.aligned.m16n8k16.row.col.f32.f16.f16.f32 "
        "{%0,%1,%2,%3}, {%4,%5,%6,%7}, {%8,%9}, {%0,%1,%2,%3};"
        : "+f"(d[0]), "+f"(d[1]), "+f"(d[2]), "+f"(d[3])
        : "r"(a[0]), "r"(a[1]), "r"(a[2]), "r"(a[3]), "r"(b[0]), "r"(b[1]));
}

// strict ordering: higher value wins; ties -> lower index (matches lax.top_k)
__device__ __forceinline__ bool better(float av, int ai, float bv, int bi) {
    return (av > bv) || (av == bv && ai < bi);
}
__device__ __forceinline__ void topk_insert(float* tv, int* ti, float s, int idx) {
    if (!better(s, idx, tv[TOPK - 1], ti[TOPK - 1])) return;
    int pos = TOPK - 1;
    #pragma unroll
    for (int it = 0; it < TOPK - 1; it++) {
        if (pos > 0 && better(s, idx, tv[pos - 1], ti[pos - 1])) {
            tv[pos] = tv[pos - 1]; ti[pos] = ti[pos - 1]; pos--;
        }
    }
    tv[pos] = s; ti[pos] = idx;
}

// issue cp.async for one B chunk image (16KB, 4x16B per thread)
__device__ __forceinline__ void issue_B(uint32_t bufS, int chunk, int tid) {
    const char* src = (const char*)g_qsw4 + (size_t)chunk * B_CHUNK;
    #pragma unroll
    for (int j = 0; j < 4; j++) {
        uint32_t dst = bufS + (uint32_t)((tid + j * NTHREADS) * 16);
        asm volatile("cp.async.ca.shared.global [%0], [%1], 16;"
                     :: "r"(dst), "l"(src + (tid + j * NTHREADS) * 16));
    }
}

// per-lane A fragment fp32 load: rows {r0,r0+8}, col pairs {c0,c0+8}
__device__ __forceinline__ void ldgA(float2* f, const float* __restrict__ emb,
                                     int docbase, int k0, int ndocs,
                                     int w, int gr, int gc) {
    int r0 = docbase + w * 16 + gr;
    int r1 = r0 + 8;
    const float* p0 = emb + (size_t)r0 * DIM + k0 + gc;
    const float* p1 = emb + (size_t)r1 * DIM + k0 + gc;
    float2 z = make_float2(0.f, 0.f);
    f[0] = (r0 < ndocs) ? __ldcg((const float2*)p0)       : z;   // frag reg0 (rows 0-7, cols 0-7)
    f[1] = (r1 < ndocs) ? __ldcg((const float2*)p1)       : z;   // frag reg1 (rows 8-15, cols 0-7)
    f[2] = (r0 < ndocs) ? __ldcg((const float2*)(p0 + 8)) : z;   // frag reg2 (rows 0-7, cols 8-15)
    f[3] = (r1 < ndocs) ? __ldcg((const float2*)(p1 + 8)) : z;   // frag reg3 (rows 8-15, cols 8-15)
}
// convert fp32 fragment pairs -> hi/mid fp16 fragment regs
__device__ __forceinline__ void convA(const float2* f, uint32_t* Ahi, uint32_t* Amd) {
    #pragma unroll
    for (int j = 0; j < 4; j++) {
        __half2 h = __floats2half2_rn(f[j].x, f[j].y);
        float rx = f[j].x - __low2float(h);
        float ry = f[j].y - __high2float(h);
        __half2 m = __floats2half2_rn(rx, ry);
        Ahi[j] = *(const uint32_t*)&h;
        Amd[j] = *(const uint32_t*)&m;
    }
}

// ---------------- kernel 1: q = query @ W^T + b -> 2 fp16 splits, pre-swizzled tiles ----------------
#define QP_KC 64
#define QP_ROWS 8
__global__ __launch_bounds__(256) void qproj_kernel(
    const float* __restrict__ query, const float* __restrict__ W, const float* __restrict__ bias)
{
    __shared__ float sW[QP_ROWS][QP_KC];
    __shared__ float sQ[QN][QP_KC + 1];

    int tid = threadIdx.x;
    int dbase = blockIdx.x * QP_ROWS;
    int q  = tid & 63;
    int dg = tid >> 6;

    float acc[2] = {0.f, 0.f};

    for (int kb = 0; kb < DIM; kb += QP_KC) {
        __syncthreads();
        if (tid < QP_ROWS * 16) {
            int row = tid >> 4, c4 = tid & 15;
            float4 v = *(const float4*)&W[(size_t)(dbase + row) * DIM + kb + c4 * 4];
            sW[row][c4*4+0]=v.x; sW[row][c4*4+1]=v.y; sW[row][c4*4+2]=v.z; sW[row][c4*4+3]=v.w;
        }
        #pragma unroll
        for (int i = 0; i < 4; i++) {
            int idx = tid + i * 256;
            int row = idx >> 4, c4 = idx & 15;
            float4 v = *(const float4*)&query[(size_t)row * DIM + kb + c4 * 4];
            sQ[row][c4*4+0]=v.x; sQ[row][c4*4+1]=v.y; sQ[row][c4*4+2]=v.z; sQ[row][c4*4+3]=v.w;
        }
        __syncthreads();
        #pragma unroll 8
        for (int k = 0; k < QP_KC; k++) {
            float qv = sQ[q][k];
            #pragma unroll
            for (int i = 0; i < 2; i++) acc[i] += sW[dg * 2 + i][k] * qv;
        }
    }

    unsigned char* qsw = (unsigned char*)g_qsw4;
    #pragma unroll
    for (int i = 0; i < 2; i++) {
        int d = dbase + dg * 2 + i;
        float val = acc[i] + bias[d];
        __half h = __float2half_rn(val);
        float r  = val - __half2float(h);            // exact residual
        __half m = __float2half_rn(r);
        int cch = d >> 6;
        int rr  = d & 63;
        uint32_t off = SW128((uint32_t)(rr * 128 + q * 2));
        *(unsigned short*)(qsw + cch * B_CHUNK + off)           = __half_as_ushort(h);
        *(unsigned short*)(qsw + cch * B_CHUNK + B_SPLIT + off) = __half_as_ushort(m);
    }
}

// ---------------- kernel 2: A-in-registers fp16 2-split scores + fused top-5 ----------------
// warp w owns rows [w*16, w*16+16) x all 64 queries. A: DRAM -> regs (no smem).
__global__ __launch_bounds__(NTHREADS, 2) void score_topk_kernel(
    const float* __restrict__ emb, int ndocs, int ntiles)
{
    extern __shared__ char dynsmem[];
    __shared__ float topv[QN][TOPK];
    __shared__ int   topi[QN][TOPK];

    int tid  = threadIdx.x;
    int lane = tid & 31;
    int w    = tid >> 5;          // 0..7 -> m-group
    int gr   = lane >> 2;         // 0..7
    int gc   = (lane & 3) * 2;    // 0,2,4,6
    int l15  = lane & 15;
    int lh8  = (lane >> 4) * 8;

    uint32_t raw  = smem_u32(dynsmem);
    uint32_t base = (raw + 1023) & ~1023u;
    char*    pool = dynsmem + (base - raw);
    float*   stage = (float*)(pool + OFF_STAGE);

    if (tid < QN) {
        #pragma unroll
        for (int j = 0; j < TOPK; j++) { topv[tid][j] = -FLT_MAX; topi[tid][j] = 0x7fffffff; }
    }

    float acc[8][4];
    #pragma unroll
    for (int ni = 0; ni < 8; ni++)
        #pragma unroll
        for (int r = 0; r < 4; r++) acc[ni][r] = 0.f;

    int t = blockIdx.x;
    if (t < ntiles) {
        // prologue: B chunk 0 -> buf0; A fp32 for (t, c=0, ks=0)
        issue_B(base, 0, tid);
        asm volatile("cp.async.commit_group;" ::: "memory");
        float2 f[4];
        ldgA(f, emb, t * TILE_M, 0, ndocs, w, gr, gc);

        int c = 0, p = 0;
        while (true) {
            int cn = c + 1, tn = t;
            bool more = true;
            if (cn == NCHUNK) { cn = 0; tn = t + gridDim.x; more = (tn < ntiles); }

            asm volatile("cp.async.wait_group 0;" ::: "memory");
            __syncthreads();                        // B buf p visible to all warps

            if (more) issue_B(base + (uint32_t)((p ^ 1) * B_CHUNK), cn, tid);
            asm volatile("cp.async.commit_group;" ::: "memory");

            // L2 prefetch for next chunk's A rows (256B per row, 2 lines -> 1 per thread)
            if (more) {
                int row  = tid >> 1;
                int gdoc = tn * TILE_M + row;
                if (gdoc < ndocs) {
                    const float* pf = emb + (size_t)gdoc * DIM + cn * CHUNK_K + (tid & 1) * 32;
                    asm volatile("prefetch.global.L2 [%0];" :: "l"(pf));
                }
            }

            uint32_t bufB = base + (uint32_t)(p * B_CHUNK);

            #pragma unroll
            for (int ks = 0; ks < KSTEPS; ks++) {
                // convert current A fp32 -> hi/mid fragments
                uint32_t Ahi[4], Amd[4];
                convA(f, Ahi, Amd);

                // prefetch next A fp32 (next ks, or next chunk/tile's ks0)
                if (ks < KSTEPS - 1)
                    ldgA(f, emb, t * TILE_M, c * CHUNK_K + (ks + 1) * 16, ndocs, w, gr, gc);
                else if (more)
                    ldgA(f, emb, tn * TILE_M, cn * CHUNK_K, ndocs, w, gr, gc);

                // B fragments: full N=64, both splits
                uint32_t Bf[2][16];
                #pragma unroll
                for (int s = 0; s < 2; s++)
                    #pragma unroll
                    for (int nb = 0; nb < 4; nb++)
                        ldsm_x4_t(&Bf[s][nb * 4],
                            bufB + s * B_SPLIT +
                            SW128((uint32_t)((ks * 16 + l15) * 128 + (nb * 16 + lh8) * 2)));

                // 3 terms: hh, hm, mh
                #pragma unroll
                for (int ni = 0; ni < 8; ni++) mma_fp16(acc[ni], Ahi, &Bf[0][ni * 2]);
                #pragma unroll
                for (int ni = 0; ni < 8; ni++) mma_fp16(acc[ni], Ahi, &Bf[1][ni * 2]);
                #pragma unroll
                for (int ni = 0; ni < 8; ni++) mma_fp16(acc[ni], Amd, &Bf[0][ni * 2]);
            }

            // tile epilogue
            if (c == NCHUNK - 1) {
                #pragma unroll
                for (int ni = 0; ni < 8; ni++) {
                    int row = w * 16 + gr;
                    int col = ni * 8 + gc;
                    *(float2*)&stage[row * STAGE_STRIDE + col] =
                        make_float2(acc[ni][0], acc[ni][1]);
                    *(float2*)&stage[(row + 8) * STAGE_STRIDE + col] =
                        make_float2(acc[ni][2], acc[ni][3]);
                }
                __syncthreads();
                if (tid < QN) {
                    float* tv = topv[tid];
                    int*   ti = topi[tid];
                    int docbase = t * TILE_M;
                    int dmax = ndocs - docbase;
                    if (dmax > TILE_M) dmax = TILE_M;
                    for (int dl = 0; dl < dmax; dl++) {
                        float s = stage[dl * STAGE_STRIDE + tid];
                        if (s > tv[TOPK - 1]) topk_insert(tv, ti, s, docbase + dl);
                    }
                }
                #pragma unroll
                for (int ni = 0; ni < 8; ni++)
                    #pragma unroll
                    for (int r = 0; r < 4; r++) acc[ni][r] = 0.f;
            }

            if (!more) break;
            t = tn; c = cn; p ^= 1;
        }
    }

    __syncthreads();
    if (tid < QN) {
        #pragma unroll
        for (int j = 0; j < TOPK; j++) {
            size_t o = ((size_t)blockIdx.x * QN + tid) * TOPK + j;
            g_cand_val[o] = topv[tid][j];
            g_cand_idx[o] = topi[tid][j];
        }
    }
}

// ---------------- kernel 3: global candidate merge -> output (float indices) ----------------
__global__ __launch_bounds__(128) void final_topk_kernel(float* __restrict__ out, int nblocks)
{
    __shared__ float sval[128 * TOPK];
    __shared__ int   sidx[128 * TOPK];
    int q   = blockIdx.x;
    int tid = threadIdx.x;

    float lv[TOPK]; int li[TOPK];
    #pragma unroll
    for (int j = 0; j < TOPK; j++) { lv[j] = -FLT_MAX; li[j] = 0x7fffffff; }

    for (int b = tid; b < nblocks; b += 128) {
        size_t o = ((size_t)b * QN + q) * TOPK;
        #pragma unroll
        for (int j = 0; j < TOPK; j++)
            topk_insert(lv, li, g_cand_val[o + j], g_cand_idx[o + j]);
    }
    #pragma unroll
    for (int j = 0; j < TOPK; j++) { sval[tid * TOPK + j] = lv[j]; sidx[tid * TOPK + j] = li[j]; }
    __syncthreads();

    if (tid == 0) {
        float fv[TOPK]; int fi[TOPK];
        #pragma unroll
        for (int j = 0; j < TOPK; j++) { fv[j] = -FLT_MAX; fi[j] = 0x7fffffff; }
        for (int e = 0; e < 128 * TOPK; e++)
            topk_insert(fv, fi, sval[e], sidx[e]);
        #pragma unroll
        for (int j = 0; j < TOPK; j++) out[q * TOPK + j] = (float)fi[j];
    }
}

// ---------------- launch ----------------
// Inputs identified BY ELEMENT COUNT:
//   b = 768, query = 49152, W = 589824, block_emb = largest, top_k scalar ignored (TOPK=5 per out_size).
extern "C" void kernel_launch(void* const* d_in, const int* in_sizes, int n_in,
                              void* d_out, int out_size)
{
    const float *query = nullptr, *W = nullptr, *bias = nullptr, *emb = nullptr;
    int ndocs = 0;
    for (int i = 0; i < n_in; i++) {
        int sz = in_sizes[i];
        if      (sz == DIM)        bias  = (const float*)d_in[i];
        else if (sz == QN * DIM)   query = (const float*)d_in[i];
        else if (sz == DIM * DIM)  W     = (const float*)d_in[i];
        else if (sz >  DIM * DIM) { emb  = (const float*)d_in[i]; ndocs = sz / DIM; }
    }
    if (!query || !W || !bias || !emb || ndocs <= 0) return;

    int ntiles = (ndocs + TILE_M - 1) / TILE_M;

    cudaFuncSetAttribute(score_topk_kernel, cudaFuncAttributeMaxDynamicSharedMemorySize, SMEM_DYN);

    qproj_kernel<<<DIM / QP_ROWS, 256>>>(query, W, bias);
    score_topk_kernel<<<NBLOCKS, NTHREADS, SMEM_DYN>>>(emb, ndocs, ntiles);
    final_topk_kernel<<<QN, 128>>>((float*)d_out, NBLOCKS);
}